// round 2
// baseline (speedup 1.0000x reference)
#include <cuda_runtime.h>
#include <cstdint>

// Grouped GEMM out[16384,4096] : 8 groups of [2048 x 4096] @ w[g][4096 x 4096].
// Base-sm_103 build (no 'a' features) -> legacy tensor path: mma.sync tf32 (HMMA),
// cp.async 4-stage pipeline, padded smem layouts (conflict-free fragment LDS),
// explicit cvt.rna.tf32.f32 to avoid truncation bias.

#define TOK   16384
#define INF   4096
#define OUTF  4096

#define BM    128
#define BN    256
#define BK    32
#define KT    (INF / BK)          // 128 k-tiles

#define SA    36                  // A smem row stride (floats): 32 used + 4 pad
#define SB    264                 // B smem row stride (floats): 256 used + 8 pad
#define A_FLOATS (BM * SA)        // 4608
#define B_FLOATS (BK * SB)        // 8448
#define STAGE_FLOATS (A_FLOATS + B_FLOATS)   // 13056
#define STAGES 4
#define SMEM_BYTES (STAGES * STAGE_FLOATS * 4)  // 208896
#define NTHREADS 512

__device__ __forceinline__ uint32_t f2tf32(float x) {
    uint32_t u;
    asm("cvt.rna.tf32.f32 %0, %1;" : "=r"(u) : "f"(x));
    return u;
}

__device__ __forceinline__ uint32_t smem_u32(const void* p) {
    uint32_t a;
    asm("{ .reg .u64 t; cvta.to.shared.u64 t, %1; cvt.u32.u64 %0, t; }"
        : "=r"(a) : "l"(p));
    return a;
}

#define CPA16(dst, src) \
    asm volatile("cp.async.cg.shared.global [%0], [%1], 16;" :: "r"(dst), "l"(src))

__device__ __forceinline__ void mma_tf32(float* d, const uint32_t* a, const uint32_t* b) {
    asm volatile(
        "mma.sync.aligned.m16n8k8.row.col.f32.tf32.tf32.f32 "
        "{%0,%1,%2,%3}, {%4,%5,%6,%7}, {%8,%9}, {%0,%1,%2,%3};"
        : "+f"(d[0]), "+f"(d[1]), "+f"(d[2]), "+f"(d[3])
        : "r"(a[0]), "r"(a[1]), "r"(a[2]), "r"(a[3]), "r"(b[0]), "r"(b[1]));
}

extern "C" __global__ void __launch_bounds__(NTHREADS, 1)
grouped_gemm_hmma(const float* __restrict__ x, const float* __restrict__ w,
                  float* __restrict__ out) {
    extern __shared__ float sm[];
    const uint32_t smb = smem_u32(sm);

    const int t = threadIdx.x;
    const int lane = t & 31;
    const int wid = t >> 5;          // 16 warps: 4 (m) x 4 (n)
    const int wm = wid & 3;          // warp m-tile of 32 rows
    const int wn = wid >> 2;         // warp n-tile of 64 cols

    const int bid = blockIdx.x;
    const int nt = bid & 15;         // nt-inner: concurrent CTAs share A panels in L2
    const int mt = bid >> 4;
    const int g  = mt >> 4;          // 2048 rows per group = 16 m-tiles

    const float* xg = x + (size_t)mt * BM * INF;
    const float* wg = w + (size_t)g * INF * OUTF + (size_t)nt * BN;

    // ---- async tile loader: one commit group per k-tile ----
    auto load_tile = [&](int kt) {
        const uint32_t sb = smb + (uint32_t)(kt & 3) * (STAGE_FLOATS * 4);
        // A: 128 rows x 32 floats -> 1024 x 16B chunks; id = row*8 + kc
#pragma unroll
        for (int i = 0; i < 2; i++) {
            int id = t + i * NTHREADS;
            int row = id >> 3, kc = id & 7;
            CPA16(sb + (uint32_t)row * (SA * 4) + (uint32_t)kc * 16,
                  xg + (size_t)row * INF + (size_t)kt * BK + kc * 4);
        }
        // B: 32 rows (k) x 256 floats -> 2048 x 16B chunks; id = k*64 + nc
#pragma unroll
        for (int i = 0; i < 4; i++) {
            int id = t + i * NTHREADS;
            int k = id >> 6, nc = id & 63;
            CPA16(sb + (uint32_t)(A_FLOATS * 4) + (uint32_t)k * (SB * 4) + (uint32_t)nc * 16,
                  wg + (size_t)((size_t)kt * BK + k) * OUTF + nc * 4);
        }
        asm volatile("cp.async.commit_group;" ::: "memory");
    };

    load_tile(0);
    load_tile(1);
    load_tile(2);

    float acc[2][8][4];
#pragma unroll
    for (int mi = 0; mi < 2; mi++)
#pragma unroll
        for (int ni = 0; ni < 8; ni++)
#pragma unroll
            for (int q = 0; q < 4; q++) acc[mi][ni][q] = 0.0f;

    // Per-thread fragment base offsets (float indices within a stage)
    const int a_off = (wm * 32 + (lane >> 2)) * SA + (lane & 3);
    const int b_off = A_FLOATS + (lane & 3) * SB + wn * 64 + (lane >> 2);

    for (int kt = 0; kt < KT; kt++) {
        asm volatile("cp.async.wait_group 2;" ::: "memory");
        __syncthreads();   // tile kt visible to all; buffer (kt+3)%4 free of readers

        if (kt + 3 < KT) load_tile(kt + 3);

        const float* aP = sm + (size_t)(kt & 3) * STAGE_FLOATS + a_off;
        const float* bP = sm + (size_t)(kt & 3) * STAGE_FLOATS + b_off;

#pragma unroll
        for (int ks = 0; ks < 4; ks++) {
            uint32_t a[2][4], b[8][2];
#pragma unroll
            for (int mi = 0; mi < 2; mi++) {
                const float* p = aP + ks * 8 + mi * (16 * SA);
                a[mi][0] = f2tf32(p[0]);
                a[mi][1] = f2tf32(p[8 * SA]);
                a[mi][2] = f2tf32(p[4]);
                a[mi][3] = f2tf32(p[8 * SA + 4]);
            }
#pragma unroll
            for (int ni = 0; ni < 8; ni++) {
                const float* p = bP + ks * (8 * SB) + ni * 8;
                b[ni][0] = f2tf32(p[0]);
                b[ni][1] = f2tf32(p[4 * SB]);
            }
#pragma unroll
            for (int mi = 0; mi < 2; mi++)
#pragma unroll
                for (int ni = 0; ni < 8; ni++)
                    mma_tf32(acc[mi][ni], a[mi], b[ni]);
        }
    }

    // ---- epilogue: register accumulators -> gmem (float2 stores, coalesced) ----
    const int r0 = mt * BM + wm * 32 + (lane >> 2);
    const int c0 = nt * BN + wn * 64 + 2 * (lane & 3);
#pragma unroll
    for (int mi = 0; mi < 2; mi++) {
#pragma unroll
        for (int ni = 0; ni < 8; ni++) {
            float2 v0 = make_float2(acc[mi][ni][0], acc[mi][ni][1]);
            float2 v1 = make_float2(acc[mi][ni][2], acc[mi][ni][3]);
            size_t base = (size_t)(r0 + mi * 16) * OUTF + c0 + ni * 8;
            *reinterpret_cast<float2*>(out + base) = v0;
            *reinterpret_cast<float2*>(out + base + 8 * OUTF) = v1;
        }
    }
}

extern "C" void kernel_launch(void* const* d_in, const int* in_sizes, int n_in,
                              void* d_out, int out_size) {
    const float* x = (const float*)d_in[0];
    const float* w = (const float*)d_in[1];
    float* out = (float*)d_out;
    cudaFuncSetAttribute(grouped_gemm_hmma,
                         cudaFuncAttributeMaxDynamicSharedMemorySize, SMEM_BYTES);
    dim3 grid((TOK / BM) * (OUTF / BN));   // 128 * 16 = 2048
    grouped_gemm_hmma<<<grid, NTHREADS, SMEM_BYTES>>>(x, w, out);
}

// round 3
// speedup vs baseline: 2.1739x; 2.1739x over previous
#include <cuda_runtime.h>
#include <cuda_fp16.h>
#include <cstdint>

// Grouped GEMM out[16384,4096]: 8 groups of [2048x4096] @ w[g][4096x4096], fp32 io.
// Base-sm_103 build (no 'a' ISA). Strategy:
//   pass 1: convert x,w fp32 -> fp16 into __device__ scratch (tensor-grade mantissa:
//           fp16 m10 == tf32 m10; fp32 accumulate keeps rel_err ~3e-4)
//   pass 2: fp16 HMMA (mma.m16n8k16) GEMM, cp.async 4-stage pipeline, ldmatrix
//           fragment loads, padded conflict-free smem.

#define TOK   16384
#define INF   4096
#define OUTF  4096
#define NG    8

#define BM    128
#define BN    256
#define BK    64
#define KT    (INF / BK)          // 64 k-tiles

#define SAH   72                  // A smem row stride in halves (64 + 8 pad) -> 144B
#define SBH   264                 // B smem row stride in halves (256 + 8 pad) -> 528B
#define A_BYTES (BM * SAH * 2)    // 18432
#define B_BYTES (BK * SBH * 2)    // 33792
#define STAGE_BYTES (A_BYTES + B_BYTES)       // 52224
#define STAGES 4
#define SMEM_BYTES (STAGES * STAGE_BYTES)     // 208896
#define NTHREADS 512

__device__ __align__(16) __half g_xh[(size_t)TOK * INF];        // 128 MB scratch
__device__ __align__(16) __half g_wh[(size_t)NG * INF * OUTF];  // 256 MB scratch

// ---------------- pass 1: fp32 -> fp16 ----------------
__global__ void cvt_f32_f16(const float* __restrict__ src, __half* __restrict__ dst,
                            size_t n8) {
    size_t i = (size_t)blockIdx.x * blockDim.x + threadIdx.x;
    const size_t stride = (size_t)gridDim.x * blockDim.x;
    for (; i < n8; i += stride) {
        float4 v0 = reinterpret_cast<const float4*>(src)[2 * i];
        float4 v1 = reinterpret_cast<const float4*>(src)[2 * i + 1];
        __half2 h0 = __floats2half2_rn(v0.x, v0.y);
        __half2 h1 = __floats2half2_rn(v0.z, v0.w);
        __half2 h2 = __floats2half2_rn(v1.x, v1.y);
        __half2 h3 = __floats2half2_rn(v1.z, v1.w);
        uint4 u;
        u.x = *reinterpret_cast<uint32_t*>(&h0);
        u.y = *reinterpret_cast<uint32_t*>(&h1);
        u.z = *reinterpret_cast<uint32_t*>(&h2);
        u.w = *reinterpret_cast<uint32_t*>(&h3);
        reinterpret_cast<uint4*>(dst)[i] = u;
    }
}

// ---------------- pass 2: fp16 HMMA GEMM ----------------
__device__ __forceinline__ uint32_t smem_u32(const void* p) {
    uint32_t a;
    asm("{ .reg .u64 t; cvta.to.shared.u64 t, %1; cvt.u32.u64 %0, t; }"
        : "=r"(a) : "l"(p));
    return a;
}

#define CPA16(dst, src) \
    asm volatile("cp.async.cg.shared.global [%0], [%1], 16;" :: "r"(dst), "l"(src))

#define LDSM_X4(r0, r1, r2, r3, a)                                              \
    asm volatile("ldmatrix.sync.aligned.m8n8.x4.shared.b16 {%0,%1,%2,%3}, [%4];" \
                 : "=r"(r0), "=r"(r1), "=r"(r2), "=r"(r3) : "r"(a))

#define LDSM_X4T(r0, r1, r2, r3, a)                                                   \
    asm volatile("ldmatrix.sync.aligned.m8n8.x4.trans.shared.b16 {%0,%1,%2,%3}, [%4];" \
                 : "=r"(r0), "=r"(r1), "=r"(r2), "=r"(r3) : "r"(a))

__device__ __forceinline__ void mma16816(float* d, const uint32_t* a, const uint32_t* b) {
    asm volatile(
        "mma.sync.aligned.m16n8k16.row.col.f32.f16.f16.f32 "
        "{%0,%1,%2,%3}, {%4,%5,%6,%7}, {%8,%9}, {%0,%1,%2,%3};"
        : "+f"(d[0]), "+f"(d[1]), "+f"(d[2]), "+f"(d[3])
        : "r"(a[0]), "r"(a[1]), "r"(a[2]), "r"(a[3]), "r"(b[0]), "r"(b[1]));
}

extern "C" __global__ void __launch_bounds__(NTHREADS, 1)
grouped_gemm_f16(float* __restrict__ out) {
    extern __shared__ char sm[];
    const uint32_t smb = smem_u32(sm);

    const int t = threadIdx.x;
    const int lane = t & 31;
    const int wid = t >> 5;          // 16 warps: 4 (m) x 4 (n)
    const int wm = wid & 3;          // 32-row warp tile
    const int wn = wid >> 2;         // 64-col warp tile

    const int bid = blockIdx.x;
    const int nt = bid & 15;         // nt-inner: wave shares A panels in L2
    const int mt = bid >> 4;
    const int g  = mt >> 4;

    const __half* xg = g_xh + (size_t)mt * BM * INF;
    const __half* wg = g_wh + (size_t)g * INF * OUTF + (size_t)nt * BN;

    auto load_tile = [&](int kt) {
        const uint32_t sb = smb + (uint32_t)(kt & 3) * STAGE_BYTES;
        // A: 128 rows x 128B -> 1024 chunks; id = row*8 + kc
#pragma unroll
        for (int i = 0; i < 2; i++) {
            int id = t + i * NTHREADS;
            int row = id >> 3, kc = id & 7;
            CPA16(sb + (uint32_t)row * (SAH * 2) + (uint32_t)kc * 16,
                  xg + (size_t)row * INF + (size_t)kt * BK + kc * 8);
        }
        // B: 64 rows x 512B -> 2048 chunks; id = k*32 + nc
#pragma unroll
        for (int i = 0; i < 4; i++) {
            int id = t + i * NTHREADS;
            int k = id >> 5, nc = id & 31;
            CPA16(sb + A_BYTES + (uint32_t)k * (SBH * 2) + (uint32_t)nc * 16,
                  wg + (size_t)((size_t)kt * BK + k) * OUTF + nc * 8);
        }
        asm volatile("cp.async.commit_group;" ::: "memory");
    };

    load_tile(0);
    load_tile(1);
    load_tile(2);

    float acc[2][8][4];
#pragma unroll
    for (int mi = 0; mi < 2; mi++)
#pragma unroll
        for (int ni = 0; ni < 8; ni++)
#pragma unroll
            for (int q = 0; q < 4; q++) acc[mi][ni][q] = 0.0f;

    // ldmatrix per-lane base offsets (bytes within stage)
    // A x4: lanes 0-7 rows m0+0..7 @k0 | 8-15 rows m0+8..15 @k0 | 16-23 rows m0+0..7 @k0+8 | 24-31 rows +8
    const uint32_t aOff =
        (uint32_t)(wm * 32 + (lane & 7) + ((lane >> 3) & 1) * 8) * (SAH * 2) +
        (uint32_t)((lane >> 4) & 1) * 16;
    // B x4.trans: lanes 0-7 k0+0..7 @n0 | 8-15 k0+8..15 @n0 | 16-23 k0+0..7 @n0+8 | 24-31 +8
    const uint32_t bOff = A_BYTES +
        (uint32_t)((lane & 7) + ((lane >> 3) & 1) * 8) * (SBH * 2) +
        (uint32_t)(wn * 64 + ((lane >> 4) & 1) * 8) * 2;

    for (int kt = 0; kt < KT; kt++) {
        asm volatile("cp.async.wait_group 2;" ::: "memory");
        __syncthreads();   // tile kt visible; stage (kt+3)&3 has no active readers

        if (kt + 3 < KT) load_tile(kt + 3);
        else asm volatile("cp.async.commit_group;" ::: "memory");  // keep group count uniform

        const uint32_t stage = smb + (uint32_t)(kt & 3) * STAGE_BYTES;

#pragma unroll
        for (int ks = 0; ks < 4; ks++) {   // BK=64 -> 4 x k16
            uint32_t a[2][4], b[4][4];
#pragma unroll
            for (int mi = 0; mi < 2; mi++)
                LDSM_X4(a[mi][0], a[mi][1], a[mi][2], a[mi][3],
                        stage + aOff + (uint32_t)mi * (16 * SAH * 2) + (uint32_t)ks * 32);
#pragma unroll
            for (int np = 0; np < 4; np++)
                LDSM_X4T(b[np][0], b[np][1], b[np][2], b[np][3],
                         stage + bOff + (uint32_t)ks * (16 * SBH * 2) + (uint32_t)np * 32);
#pragma unroll
            for (int mi = 0; mi < 2; mi++)
#pragma unroll
                for (int np = 0; np < 4; np++) {
                    mma16816(acc[mi][2 * np],     a[mi], &b[np][0]);
                    mma16816(acc[mi][2 * np + 1], a[mi], &b[np][2]);
                }
        }
    }

    // epilogue: m16n8 C fragment -> coalesced float2 stores
    const int r0 = mt * BM + wm * 32 + (lane >> 2);
    const int c0 = nt * BN + wn * 64 + 2 * (lane & 3);
#pragma unroll
    for (int mi = 0; mi < 2; mi++)
#pragma unroll
        for (int ni = 0; ni < 8; ni++) {
            size_t base = (size_t)(r0 + mi * 16) * OUTF + c0 + ni * 8;
            *reinterpret_cast<float2*>(out + base) =
                make_float2(acc[mi][ni][0], acc[mi][ni][1]);
            *reinterpret_cast<float2*>(out + base + 8 * OUTF) =
                make_float2(acc[mi][ni][2], acc[mi][ni][3]);
        }
}

extern "C" void kernel_launch(void* const* d_in, const int* in_sizes, int n_in,
                              void* d_out, int out_size) {
    const float* x = (const float*)d_in[0];
    const float* w = (const float*)d_in[1];
    float* out = (float*)d_out;

    __half* xh = nullptr;
    __half* wh = nullptr;
    cudaGetSymbolAddress((void**)&xh, g_xh);
    cudaGetSymbolAddress((void**)&wh, g_wh);

    cvt_f32_f16<<<4096, 256>>>(x, xh, (size_t)TOK * INF / 8);
    cvt_f32_f16<<<8192, 256>>>(w, wh, (size_t)NG * INF * OUTF / 8);

    cudaFuncSetAttribute(grouped_gemm_f16,
                         cudaFuncAttributeMaxDynamicSharedMemorySize, SMEM_BYTES);
    dim3 grid((TOK / BM) * (OUTF / BN));   // 2048
    grouped_gemm_f16<<<grid, NTHREADS, SMEM_BYTES>>>(out);
}